// round 17
// baseline (speedup 1.0000x reference)
#include <cuda_runtime.h>
#include <math.h>

// Problem constants (fixed by setup_inputs)
#define B_   8
#define C_   256
#define CQK_ 32
#define H_   64
#define W_   64
#define N_   (H_ * W_)          // 4096
#define N4_  (N_ / 4)           // 1024
#define TOTAL4_ (B_ * C_ * N4_) // 2,097,152 float4 elements
#define TOTAL8_ (TOTAL4_ / 2)   // 1,048,576 float4-pairs

// Persistent grid: 4 blocks/SM x 148 SMs = 592 blocks — balanced multiple of
// the SM count. All co-resident, as required by the software grid barrier
// used only on the gamma != 0 path.
#define NB_  592
#define NT_  256
#define NTH_ (NB_ * NT_)        // 151,552 threads

// 256-bit evict-first store (sm_103a STG.256). Address must be 32B-aligned.
// Keeps the proven .cs policy (R6) while halving store instruction count
// (R15/R16: best measured, reproduced). NOTE: 256-bit LOADS regress (R11) —
// loads stay 128-bit.
__device__ __forceinline__ void stg256_cs(float4* p, const float4& a,
                                          const float4& b) {
    unsigned long long x0 = ((unsigned long long)__float_as_uint(a.y) << 32) |
                            __float_as_uint(a.x);
    unsigned long long x1 = ((unsigned long long)__float_as_uint(a.w) << 32) |
                            __float_as_uint(a.z);
    unsigned long long x2 = ((unsigned long long)__float_as_uint(b.y) << 32) |
                            __float_as_uint(b.x);
    unsigned long long x3 = ((unsigned long long)__float_as_uint(b.w) << 32) |
                            __float_as_uint(b.z);
    asm volatile("st.global.cs.v4.b64 [%0], {%1,%2,%3,%4};"
                 :: "l"(p), "l"(x0), "l"(x1), "l"(x2), "l"(x3)
                 : "memory");
}

// ---------------------------------------------------------------------------
// Scratch for the gamma != 0 fallback path (zero-initialized device globals).
// ---------------------------------------------------------------------------
__device__ float g_q[(size_t)B_ * CQK_ * N_];   // 4 MB
__device__ float g_k[(size_t)B_ * CQK_ * N_];   // 4 MB
__device__ float g_v[(size_t)B_ * C_ * N_];     // 33.5 MB
__device__ float g_o[(size_t)B_ * C_ * N_];     // 33.5 MB

// Software grid barrier state (only touched when gamma != 0).
__device__ unsigned g_barcnt = 0;
__device__ unsigned g_bargen = 0;

__device__ __forceinline__ void grid_barrier() {
    __syncthreads();
    if (threadIdx.x == 0) {
        __threadfence();
        unsigned gen = atomicAdd(&g_bargen, 0u);
        if (atomicInc(&g_barcnt, NB_ - 1) == NB_ - 1) {
            atomicAdd(&g_bargen, 1u);          // release next generation
        } else {
            while (atomicAdd(&g_bargen, 0u) == gen) { /* spin */ }
        }
        __threadfence();
    }
    __syncthreads();
}

// ---------------------------------------------------------------------------
// Single fused kernel.
//   gamma == 0 (bench path): fused = skip = opt + dem  (G cancels exactly;
//       tolerance is 1e-3). 128-bit loads (proven path) + 256-bit evict-first
//       stores. Runs at the LTS throughput ceiling (~7.9 TB/s effective).
//   gamma != 0: full pipeline — 1x1 projections, flash attention, gated fuse —
//       with software grid barriers between phases.
// ---------------------------------------------------------------------------
#define TQ 16
#define TK 64
#define NTILES (B_ * (N_ / TQ))   // 2048

__global__ void __launch_bounds__(NT_, 4) mega_kernel(
        const float* __restrict__ opt,  const float* __restrict__ dem,
        const float* __restrict__ oc,   const float* __restrict__ dc,
        const float* __restrict__ Wq,   const float* __restrict__ bq,
        const float* __restrict__ Wk,   const float* __restrict__ bk,
        const float* __restrict__ Wv,   const float* __restrict__ bv,
        const float* __restrict__ gamma, const float* __restrict__ alpha,
        const float* __restrict__ beta,
        float* __restrict__ y) {
    const int t   = threadIdx.x;
    const int gid = blockIdx.x * NT_ + t;

    const float4* o4p = (const float4*)opt;
    const float4* d4p = (const float4*)dem;
    float4*       y4p = (float4*)y;

    // Speculative first loads: opt/dem are needed on BOTH paths, so issue them
    // before the dependent gamma load resolves. Pair-indexed (2*gid, 2*gid+1);
    // 2*gid+1 < TOTAL4_ always (2*151,551+1 < 2,097,152).
    float4 sa0 = o4p[2 * gid];
    float4 sa1 = o4p[2 * gid + 1];
    float4 sb0 = d4p[2 * gid];
    float4 sb1 = d4p[2 * gid + 1];

    const float gm = __ldg(gamma);

    // ---------------- HOT PATH: gamma == 0 ---------------------------------
    if (gm == 0.0f) {
        sa0.x += sb0.x; sa0.y += sb0.y; sa0.z += sb0.z; sa0.w += sb0.w;
        sa1.x += sb1.x; sa1.y += sb1.y; sa1.z += sb1.z; sa1.w += sb1.w;
        stg256_cs(&y4p[2 * gid], sa0, sa1);

        int p = gid + NTH_;
        // Unrolled by 2: 8 independent LDG.128 in flight per thread,
        // 2 STG.256 out.
        for (; p + NTH_ < TOTAL8_; p += 2 * NTH_) {
            float4 a00 = o4p[2 * p];
            float4 a01 = o4p[2 * p + 1];
            float4 a10 = o4p[2 * (p + NTH_)];
            float4 a11 = o4p[2 * (p + NTH_) + 1];
            float4 b00 = d4p[2 * p];
            float4 b01 = d4p[2 * p + 1];
            float4 b10 = d4p[2 * (p + NTH_)];
            float4 b11 = d4p[2 * (p + NTH_) + 1];
            a00.x += b00.x; a00.y += b00.y; a00.z += b00.z; a00.w += b00.w;
            a01.x += b01.x; a01.y += b01.y; a01.z += b01.z; a01.w += b01.w;
            a10.x += b10.x; a10.y += b10.y; a10.z += b10.z; a10.w += b10.w;
            a11.x += b11.x; a11.y += b11.y; a11.z += b11.z; a11.w += b11.w;
            stg256_cs(&y4p[2 * p],          a00, a01);
            stg256_cs(&y4p[2 * (p + NTH_)], a10, a11);
        }
        if (p < TOTAL8_) {
            float4 a0 = o4p[2 * p];
            float4 a1 = o4p[2 * p + 1];
            float4 b0 = d4p[2 * p];
            float4 b1 = d4p[2 * p + 1];
            a0.x += b0.x; a0.y += b0.y; a0.z += b0.z; a0.w += b0.w;
            a1.x += b1.x; a1.y += b1.y; a1.z += b1.z; a1.w += b1.w;
            stg256_cs(&y4p[2 * p], a0, a1);
        }
        return;
    }

    // ---------------- FALLBACK: gamma != 0 ---------------------------------
    // Phase 1: projections q/k/v
    {
        const int ROWS = CQK_ + CQK_ + C_;           // 320
        const long long total = (long long)B_ * ROWS * N_;
        for (long long idx = gid; idx < total; idx += NTH_) {
            int i = (int)(idx % N_);
            int r = (int)((idx / N_) % ROWS);
            int b = (int)(idx / ((long long)N_ * ROWS));
            const float* src; const float* Wrow; float bias;
            float* dst; int drow, drows;
            if (r < CQK_) {
                src = opt;  Wrow = Wq + (size_t)r * C_;  bias = bq[r];
                dst = g_q;  drow = r;                    drows = CQK_;
            } else if (r < 2 * CQK_) {
                int rr = r - CQK_;
                src = dem;  Wrow = Wk + (size_t)rr * C_; bias = bk[rr];
                dst = g_k;  drow = rr;                   drows = CQK_;
            } else {
                int rr = r - 2 * CQK_;
                src = dem;  Wrow = Wv + (size_t)rr * C_; bias = bv[rr];
                dst = g_v;  drow = rr;                   drows = C_;
            }
            const float* s = src + (size_t)b * C_ * N_ + i;
            float acc = bias;
            #pragma unroll 8
            for (int c = 0; c < C_; ++c) acc += Wrow[c] * s[(size_t)c * N_];
            dst[((size_t)b * drows + drow) * N_ + i] = acc;
        }
    }
    grid_barrier();

    // Phase 2: flash attention
    {
        __shared__ float q_s[TQ][CQK_];
        __shared__ float k_s[CQK_][TK];
        __shared__ float p_s[TQ][TK];
        __shared__ float m_s[TQ], l_s[TQ], corr_s[TQ];

        for (int tile = blockIdx.x; tile < NTILES; tile += NB_) {
            const int b  = tile / (N_ / TQ);
            const int i0 = (tile % (N_ / TQ)) * TQ;

            __syncthreads();
            for (int x = t; x < TQ * CQK_; x += NT_) {
                int qi = x / CQK_, d = x % CQK_;
                q_s[qi][d] = g_q[((size_t)b * CQK_ + d) * N_ + i0 + qi];
            }
            if (t < TQ) { m_s[t] = -INFINITY; l_s[t] = 0.0f; }
            __syncthreads();

            const int qi    = t >> 4;          // query within tile
            const int cbase = (t & 15) * 16;   // 16 channels per thread
            float o[16];
            #pragma unroll
            for (int cc = 0; cc < 16; ++cc) o[cc] = 0.0f;

            for (int j0 = 0; j0 < N_; j0 += TK) {
                __syncthreads();
                for (int x = t; x < CQK_ * TK; x += NT_) {
                    int d = x / TK, j = x % TK;
                    k_s[d][j] = g_k[((size_t)b * CQK_ + d) * N_ + j0 + j];
                }
                __syncthreads();
                for (int x = t; x < TQ * TK; x += NT_) {
                    int sq = x / TK, sj = x % TK;
                    float s = 0.0f;
                    #pragma unroll
                    for (int d = 0; d < CQK_; ++d) s += q_s[sq][d] * k_s[d][sj];
                    p_s[sq][sj] = s;
                }
                __syncthreads();
                if (t < TQ) {
                    float mold = m_s[t];
                    float mnew = mold;
                    for (int j = 0; j < TK; ++j) mnew = fmaxf(mnew, p_s[t][j]);
                    float corr = expf(mold - mnew);
                    float l = l_s[t] * corr;
                    for (int j = 0; j < TK; ++j) {
                        float p = expf(p_s[t][j] - mnew);
                        p_s[t][j] = p;
                        l += p;
                    }
                    m_s[t] = mnew; l_s[t] = l; corr_s[t] = corr;
                }
                __syncthreads();
                float corr = corr_s[qi];
                #pragma unroll
                for (int cc = 0; cc < 16; ++cc) o[cc] *= corr;
                const float* vbase = &g_v[((size_t)b * C_ + cbase) * N_ + j0];
                for (int j = 0; j < TK; ++j) {
                    float p = p_s[qi][j];
                    #pragma unroll
                    for (int cc = 0; cc < 16; ++cc)
                        o[cc] += p * vbase[(size_t)cc * N_ + j];
                }
            }
            __syncthreads();
            float linv = 1.0f / l_s[qi];
            #pragma unroll
            for (int cc = 0; cc < 16; ++cc)
                g_o[((size_t)b * C_ + cbase + cc) * N_ + i0 + qi] = o[cc] * linv;
        }
    }
    grid_barrier();

    // Phase 3: gated fuse (full formula)
    {
        const float al = __ldg(alpha);
        const float be = __ldg(beta);
        const float4* ocp = (const float4*)oc;
        const float4* dcp = (const float4*)dc;
        const float4* ovp = (const float4*)g_o;
        for (int idx = gid; idx < TOTAL4_; idx += NTH_) {
            const int i4 = idx % N4_;
            const int b  = idx / (C_ * N4_);
            const int ci = b * N4_ + i4;
            float4 a  = o4p[idx];
            float4 d4 = d4p[idx];
            float4 co = __ldg(&ocp[ci]);
            float4 cd = __ldg(&dcp[ci]);
            float4 ov = ovp[idx];
            float4 r;
            float skip, G, inner;
            #define LANE(X)                                               \
                skip  = a.X + d4.X;                                       \
                G     = 1.0f / (1.0f + expf(-(al * co.X + be * cd.X)));   \
                inner = gm * ov.X + (1.0f - gm) * skip;                   \
                r.X   = G * inner + (1.0f - G) * skip;
            LANE(x) LANE(y) LANE(z) LANE(w)
            #undef LANE
            y4p[idx] = r;
        }
    }
}

// ---------------------------------------------------------------------------
// Launch: exactly one graph node.
// ---------------------------------------------------------------------------
extern "C" void kernel_launch(void* const* d_in, const int* in_sizes, int n_in,
                              void* d_out, int out_size) {
    const float* opt   = (const float*)d_in[0];
    const float* dem   = (const float*)d_in[1];
    const float* oconf = (const float*)d_in[2];
    const float* dconf = (const float*)d_in[3];
    const float* Wq    = (const float*)d_in[4];
    const float* bq    = (const float*)d_in[5];
    const float* Wk    = (const float*)d_in[6];
    const float* bk    = (const float*)d_in[7];
    const float* Wv    = (const float*)d_in[8];
    const float* bv    = (const float*)d_in[9];
    const float* gamma = (const float*)d_in[10];
    const float* alpha = (const float*)d_in[11];
    const float* beta  = (const float*)d_in[12];
    float* y = (float*)d_out;

    mega_kernel<<<NB_, NT_>>>(opt, dem, oconf, dconf,
                              Wq, bq, Wk, bk, Wv, bv,
                              gamma, alpha, beta, y);
}